// round 13
// baseline (speedup 1.0000x reference)
#include <cuda_runtime.h>

#define BB 64
#define SS 1024
#define DD 16
#define NSPLIT 4
#define TOK (BB * SS)

// ---- packed weight layout (device staging + constant mirror) ----
#define P_WQ   0      // 32
#define P_WK   32     // 32
#define P_WV   64     // 32
#define P_BQKV 96     // 6: bq0 bq1 bk0 bk1 bv0 bv1
#define P_WU   112    // 32
#define P_BU   144    // 16
#define P_A    160    // 256  diag(g)(W1W2W3+I)
#define P_CSA  416    // 16   column sums of A'
#define P_BA   432    // 16   b@(W1W2W3+I) + bc
#define P_O    448    // 256  diag(g)Wo
#define P_CSO  704    // 16
#define P_BO   720    // 16   b@Wo + bo
#define P_TOT  736

__device__ float g_pack[P_TOT];
__constant__ float cw[P_TOT];

// Scratch
__device__ float4 g_part[NSPLIT * TOK]; // per-split partial (l, a0, a1, 0)
__device__ float2 g_q[TOK];             // q pre-scaled by 0.25*log2(e)
__device__ float4 g_kv[TOK];            // (k0,k1,v0,v1)

__device__ __forceinline__ float ex2_approx(float x) {
    float y;
    asm("ex2.approx.f32 %0, %1;" : "=f"(y) : "f"(x));
    return y;
}

// ---------------------------------------------------------------------------
// Kernel 0: pack qkv weights + fold epilogue weights into g_pack (1 block).
// ---------------------------------------------------------------------------
__global__ void __launch_bounds__(256)
precomp_kernel(const float* __restrict__ Wq, const float* __restrict__ bq,
               const float* __restrict__ Wk, const float* __restrict__ bk,
               const float* __restrict__ Wv, const float* __restrict__ bv,
               const float* __restrict__ Wu, const float* __restrict__ bu,
               const float* __restrict__ W1, const float* __restrict__ b1,
               const float* __restrict__ W2, const float* __restrict__ b2,
               const float* __restrict__ W3, const float* __restrict__ b3,
               const float* __restrict__ ln_g, const float* __restrict__ ln_b,
               const float* __restrict__ Wo, const float* __restrict__ bo)
{
    int tid = threadIdx.x;

    // qkv + Wu/bu pack
    if (tid < 32) {
        g_pack[P_WQ + tid] = Wq[tid];
        g_pack[P_WK + tid] = Wk[tid];
        g_pack[P_WV + tid] = Wv[tid];
        g_pack[P_WU + tid] = Wu[tid];
    }
    if (tid < 2) {
        g_pack[P_BQKV + tid]     = bq[tid];
        g_pack[P_BQKV + 2 + tid] = bk[tid];
        g_pack[P_BQKV + 4 + tid] = bv[tid];
    }
    if (tid < 16) g_pack[P_BU + tid] = bu[tid];

    // fold the 3 FF linears + LN gains
    __shared__ float s1[256], s2[256], s3[256], s12[256];
    __shared__ float sA[256], sAraw[256], sO[256];
    __shared__ float sbp[16], sbc[16], sg[16], sb[16];
    int r = tid >> 4, c = tid & 15;
    s1[tid] = W1[tid]; s2[tid] = W2[tid]; s3[tid] = W3[tid];
    if (tid < 16) { sg[tid] = ln_g[tid]; sb[tid] = ln_b[tid]; }
    __syncthreads();

    float acc = 0.f;
    #pragma unroll
    for (int k = 0; k < 16; k++) acc = fmaf(s1[r*16+k], s2[k*16+c], acc);
    s12[tid] = acc;
    if (tid < 16) {                 // b1@W2 + b2
        float t = b2[tid];
        #pragma unroll
        for (int k = 0; k < 16; k++) t = fmaf(b1[k], s2[k*16+tid], t);
        sbp[tid] = t;
    }
    __syncthreads();

    float w123 = 0.f;
    #pragma unroll
    for (int k = 0; k < 16; k++) w123 = fmaf(s12[r*16+k], s3[k*16+c], w123);
    float A = w123 + (r == c ? 1.0f : 0.0f);   // residual folded in
    sAraw[tid] = A;
    sA[tid] = sg[r] * A;
    sO[tid] = sg[r] * Wo[tid];
    if (tid < 16) {                 // bc = (b1@W2+b2)@W3 + b3
        float t = b3[tid];
        #pragma unroll
        for (int k = 0; k < 16; k++) t = fmaf(sbp[k], s3[k*16+tid], t);
        sbc[tid] = t;
    }
    __syncthreads();

    g_pack[P_A + tid] = sA[tid];
    g_pack[P_O + tid] = sO[tid];
    if (tid < 16) {
        float cs = 0.f, bb = sbc[tid];
        float cso = 0.f, bb2 = bo[tid];
        #pragma unroll
        for (int i = 0; i < 16; i++) {
            cs  += sA[i*16+tid];
            bb   = fmaf(sb[i], sAraw[i*16+tid], bb);
            cso += sO[i*16+tid];
            bb2  = fmaf(sb[i], Wo[i*16+tid], bb2);
        }
        g_pack[P_CSA + tid] = cs;  g_pack[P_BA + tid] = bb;
        g_pack[P_CSO + tid] = cso; g_pack[P_BO + tid] = bb2;
    }
}

// ---------------------------------------------------------------------------
// Kernel 1: QKV projection, 1 thread/token, weights from __constant__
// (uniform reads -> LDCU; no smem, no barrier).
// ---------------------------------------------------------------------------
__global__ void __launch_bounds__(256)
qkv_kernel(const float* __restrict__ x)
{
    int idx = blockIdx.x * 256 + threadIdx.x;

    const float4* xp = reinterpret_cast<const float4*>(x + idx * DD);
    float xv[16];
    #pragma unroll
    for (int c4 = 0; c4 < 4; c4++) {
        float4 v = xp[c4];
        xv[4*c4+0] = v.x; xv[4*c4+1] = v.y; xv[4*c4+2] = v.z; xv[4*c4+3] = v.w;
    }

    float q0 = cw[P_BQKV+0], q1 = cw[P_BQKV+1];
    float k0 = cw[P_BQKV+2], k1 = cw[P_BQKV+3];
    float v0 = cw[P_BQKV+4], v1 = cw[P_BQKV+5];
    #pragma unroll
    for (int i = 0; i < 16; i++) {
        float xi = xv[i];
        q0 = fmaf(xi, cw[P_WQ+i*2+0], q0);
        q1 = fmaf(xi, cw[P_WQ+i*2+1], q1);
        k0 = fmaf(xi, cw[P_WK+i*2+0], k0);
        k1 = fmaf(xi, cw[P_WK+i*2+1], k1);
        v0 = fmaf(xi, cw[P_WV+i*2+0], v0);
        v1 = fmaf(xi, cw[P_WV+i*2+1], v1);
    }

    const float SC = 0.25f * 1.4426950408889634f;  // fold scale + log2e into Q
    g_q[idx]  = make_float2(q0 * SC, q1 * SC);
    g_kv[idx] = make_float4(k0, k1, v0, v1);
}

// ---------------------------------------------------------------------------
// Kernel 2: attention, 4-way KV block split, 2 q-tokens per thread
// (R12 measured form, unchanged). Grid (2, NSPLIT, BB), 256 threads.
// ---------------------------------------------------------------------------
__global__ void __launch_bounds__(256)
attn_kernel()
{
    __shared__ float4 skv[256];   // KV quarter (4 KB)

    int tid   = threadIdx.x;
    int b     = blockIdx.z;
    int split = blockIdx.y;
    int chunk = blockIdx.x;

    int idx0 = b * SS + chunk * 512 + tid;     // token A
    int idx1 = idx0 + 256;                     // token B

    float4 kvrow = g_kv[b * SS + split * 256 + tid];
    float2 qa = g_q[idx0];
    float2 qb = g_q[idx1];

    skv[tid] = kvrow;
    __syncthreads();

    float l0 = 0.f, a00 = 0.f, a01 = 0.f;
    float l1 = 0.f, a10 = 0.f, a11 = 0.f;

    #pragma unroll 8
    for (int t = 0; t < 256; t++) {
        float4 kv = skv[t];
        float d0 = fmaf(qa.y, kv.y, qa.x * kv.x);
        float d1 = fmaf(qb.y, kv.y, qb.x * kv.x);
        float p0 = ex2_approx(d0);
        float p1 = ex2_approx(d1);
        l0 += p0;                    l1 += p1;
        a00 = fmaf(p0, kv.z, a00);   a10 = fmaf(p1, kv.z, a10);
        a01 = fmaf(p0, kv.w, a01);   a11 = fmaf(p1, kv.w, a11);
    }

    g_part[split * TOK + idx0] = make_float4(l0, a00, a01, 0.f);
    g_part[split * TOK + idx1] = make_float4(l1, a10, a11, 0.f);
}

// ---------------------------------------------------------------------------
// Kernel 3: epilogue, 1 thread/token, weights from __constant__.
// No smem, no barrier. Hoisted data loads.
// ---------------------------------------------------------------------------
__global__ void __launch_bounds__(256)
epilogue_kernel(const float* __restrict__ x, float* __restrict__ out)
{
    int idx = blockIdx.x * 256 + threadIdx.x;

    // Hoisted data loads (8 LDG.128 in flight)
    float4 p0 = g_part[0 * TOK + idx];
    float4 p1 = g_part[1 * TOK + idx];
    float4 p2 = g_part[2 * TOK + idx];
    float4 p3 = g_part[3 * TOK + idx];
    const float4* xp = reinterpret_cast<const float4*>(x + idx * DD);
    float4 xv0 = xp[0], xv1 = xp[1], xv2 = xp[2], xv3 = xp[3];

    float l  = p0.x + p1.x + p2.x + p3.x;
    float a0 = p0.y + p1.y + p2.y + p3.y;
    float a1 = p0.z + p1.z + p2.z + p3.z;
    float inv = 1.0f / l;
    float c0 = a0 * inv, c1 = a1 * inv;

    float xr[16] = {xv0.x, xv0.y, xv0.z, xv0.w, xv1.x, xv1.y, xv1.z, xv1.w,
                    xv2.x, xv2.y, xv2.z, xv2.w, xv3.x, xv3.y, xv3.z, xv3.w};

    // u = ctx @ Wu + bu + x
    float u[16];
    #pragma unroll
    for (int i = 0; i < 16; i++)
        u[i] = fmaf(c0, cw[P_WU + i], fmaf(c1, cw[P_WU + 16 + i], cw[P_BU + i])) + xr[i];

    // LN stats of u
    float su = 0.f, s2 = 0.f;
    #pragma unroll
    for (int i = 0; i < 16; i++) { su += u[i]; s2 = fmaf(u[i], u[i], s2); }
    float mu = su * (1.0f / 16.0f);
    float r  = rsqrtf(fmaf(-mu, mu, s2 * (1.0f / 16.0f)) + 1e-5f);

    // f = r*(u@A' - mu*csA) + bA
    float f[16];
    {
        float acc[16];
        #pragma unroll
        for (int j = 0; j < 16; j++) acc[j] = 0.f;
        #pragma unroll
        for (int i = 0; i < 16; i++) {
            float hv = u[i];
            #pragma unroll
            for (int j = 0; j < 16; j++)
                acc[j] = fmaf(hv, cw[P_A + i * 16 + j], acc[j]);
        }
        #pragma unroll
        for (int j = 0; j < 16; j++)
            f[j] = fmaf(r, fmaf(-mu, cw[P_CSA + j], acc[j]), cw[P_BA + j]);
    }

    // LN stats of f
    float sf = 0.f, sf2 = 0.f;
    #pragma unroll
    for (int i = 0; i < 16; i++) { sf += f[i]; sf2 = fmaf(f[i], f[i], sf2); }
    float mu2 = sf * (1.0f / 16.0f);
    float r2  = rsqrtf(fmaf(-mu2, mu2, sf2 * (1.0f / 16.0f)) + 1e-5f);

    // out = r2*(f@O' - mu2*csO) + bO
    float o[16];
    {
        float acc[16];
        #pragma unroll
        for (int j = 0; j < 16; j++) acc[j] = 0.f;
        #pragma unroll
        for (int i = 0; i < 16; i++) {
            float hv = f[i];
            #pragma unroll
            for (int j = 0; j < 16; j++)
                acc[j] = fmaf(hv, cw[P_O + i * 16 + j], acc[j]);
        }
        #pragma unroll
        for (int j = 0; j < 16; j++)
            o[j] = fmaf(r2, fmaf(-mu2, cw[P_CSO + j], acc[j]), cw[P_BO + j]);
    }

    float4* op = reinterpret_cast<float4*>(out + idx * DD);
    #pragma unroll
    for (int c4 = 0; c4 < 4; c4++)
        op[c4] = make_float4(o[4*c4+0], o[4*c4+1], o[4*c4+2], o[4*c4+3]);
}

// ---------------------------------------------------------------------------
extern "C" void kernel_launch(void* const* d_in, const int* in_sizes, int n_in,
                              void* d_out, int out_size)
{
    const float* x    = (const float*)d_in[0];
    const float* Wq   = (const float*)d_in[1];
    const float* bq   = (const float*)d_in[2];
    const float* Wk   = (const float*)d_in[3];
    const float* bk   = (const float*)d_in[4];
    const float* Wv   = (const float*)d_in[5];
    const float* bv   = (const float*)d_in[6];
    const float* Wu   = (const float*)d_in[7];
    const float* bu   = (const float*)d_in[8];
    const float* ln_g = (const float*)d_in[9];
    const float* ln_b = (const float*)d_in[10];
    const float* W1   = (const float*)d_in[11];
    const float* b1   = (const float*)d_in[12];
    const float* W2   = (const float*)d_in[13];
    const float* b2   = (const float*)d_in[14];
    const float* W3   = (const float*)d_in[15];
    const float* b3   = (const float*)d_in[16];
    const float* Wo   = (const float*)d_in[17];
    const float* bo   = (const float*)d_in[18];
    float* out = (float*)d_out;

    precomp_kernel<<<1, 256>>>(Wq, bq, Wk, bk, Wv, bv, Wu, bu,
                               W1, b1, W2, b2, W3, b3, ln_g, ln_b, Wo, bo);

    // Stage folded weights into __constant__ (graph-legal D2D memcpy node)
    void* src = nullptr;
    cudaGetSymbolAddress(&src, g_pack);
    cudaMemcpyToSymbolAsync(cw, src, sizeof(float) * P_TOT, 0,
                            cudaMemcpyDeviceToDevice, 0);

    qkv_kernel<<<TOK / 256, 256>>>(x);

    dim3 agrid(2, NSPLIT, BB);
    attn_kernel<<<agrid, 256>>>();

    epilogue_kernel<<<TOK / 256, 256>>>(x, out);
}

// round 14
// speedup vs baseline: 1.1223x; 1.1223x over previous
#include <cuda_runtime.h>
#include <cuda_fp16.h>

#define BB 64
#define SS 1024
#define DD 16
#define NSPLIT 4
#define TOK (BB * SS)

// Scratch (allocation-free rule: __device__ globals)
__device__ float4 g_part[NSPLIT * TOK]; // per-split partial (l, a0, a1, 0)
__device__ float2 g_q[TOK];             // q pre-scaled by 0.25*log2(e)
__device__ uint4  g_kvh[TOK];           // packed half2: (k0k0, k1k1, v0v0, v1v1)
__device__ float  g_A[256];             // diag(g) @ (W1W2W3 + I)
__device__ float  g_csA[16];            // column sums of g_A
__device__ float  g_bA[16];             // b @ (W1W2W3+I) + bc
__device__ float  g_O[256];             // diag(g) @ Wo
__device__ float  g_csO[16];            // column sums of g_O
__device__ float  g_bO[16];             // b @ Wo + bo

// ---------------------------------------------------------------------------
// Kernel 1: QKV projection, 1 thread/token; packs KV into duplicated half2
// lanes for the f16x2 attention loop. Last block does epilogue weight folds.
// ---------------------------------------------------------------------------
__global__ void __launch_bounds__(256)
qkv_precomp_kernel(const float* __restrict__ x,
                   const float* __restrict__ Wq, const float* __restrict__ bq,
                   const float* __restrict__ Wk, const float* __restrict__ bk,
                   const float* __restrict__ Wv, const float* __restrict__ bv,
                   const float* __restrict__ W1, const float* __restrict__ b1,
                   const float* __restrict__ W2, const float* __restrict__ b2,
                   const float* __restrict__ W3, const float* __restrict__ b3,
                   const float* __restrict__ ln_g, const float* __restrict__ ln_b,
                   const float* __restrict__ Wo, const float* __restrict__ bo)
{
    int tid = threadIdx.x;

    if (blockIdx.x == TOK / 256) {
        // ------- precompute folded epilogue weights -------
        __shared__ float s1[256], s2[256], s3[256], s12[256];
        __shared__ float sA[256], sAraw[256], sO[256];
        __shared__ float sbp[16], sbc[16], sg[16], sb[16];
        int r = tid >> 4, c = tid & 15;
        s1[tid] = W1[tid]; s2[tid] = W2[tid]; s3[tid] = W3[tid];
        if (tid < 16) { sg[tid] = ln_g[tid]; sb[tid] = ln_b[tid]; }
        __syncthreads();

        float acc = 0.f;
        #pragma unroll
        for (int k = 0; k < 16; k++) acc = fmaf(s1[r*16+k], s2[k*16+c], acc);
        s12[tid] = acc;
        if (tid < 16) {                 // b1@W2 + b2
            float t = b2[tid];
            #pragma unroll
            for (int k = 0; k < 16; k++) t = fmaf(b1[k], s2[k*16+tid], t);
            sbp[tid] = t;
        }
        __syncthreads();

        float w123 = 0.f;
        #pragma unroll
        for (int k = 0; k < 16; k++) w123 = fmaf(s12[r*16+k], s3[k*16+c], w123);
        float A = w123 + (r == c ? 1.0f : 0.0f);   // residual folded in
        sAraw[tid] = A;
        sA[tid] = sg[r] * A;
        sO[tid] = sg[r] * Wo[tid];
        if (tid < 16) {                 // bc = (b1@W2+b2)@W3 + b3
            float t = b3[tid];
            #pragma unroll
            for (int k = 0; k < 16; k++) t = fmaf(sbp[k], s3[k*16+tid], t);
            sbc[tid] = t;
        }
        __syncthreads();

        g_A[tid] = sA[tid];
        g_O[tid] = sO[tid];
        if (tid < 16) {
            float cs = 0.f, bb = sbc[tid];
            float cso = 0.f, bb2 = bo[tid];
            #pragma unroll
            for (int i = 0; i < 16; i++) {
                cs  += sA[i*16+tid];
                bb   = fmaf(sb[i], sAraw[i*16+tid], bb);
                cso += sO[i*16+tid];
                bb2  = fmaf(sb[i], Wo[i*16+tid], bb2);
            }
            g_csA[tid] = cs;  g_bA[tid] = bb;
            g_csO[tid] = cso; g_bO[tid] = bb2;
        }
        return;
    }

    // ------- QKV projection -------
    __shared__ float sw[102];
    if (tid < 32)        sw[tid] = Wq[tid];
    else if (tid < 64)   sw[tid] = Wk[tid - 32];
    else if (tid < 96)   sw[tid] = Wv[tid - 64];
    else if (tid < 98)   sw[tid] = bq[tid - 96];
    else if (tid < 100)  sw[tid] = bk[tid - 98];
    else if (tid < 102)  sw[tid] = bv[tid - 100];
    __syncthreads();

    int idx = blockIdx.x * 256 + tid;
    const float4* xp = reinterpret_cast<const float4*>(x + idx * DD);
    float xv[16];
    #pragma unroll
    for (int c4 = 0; c4 < 4; c4++) {
        float4 v = xp[c4];
        xv[4*c4+0] = v.x; xv[4*c4+1] = v.y; xv[4*c4+2] = v.z; xv[4*c4+3] = v.w;
    }

    float q0 = sw[96], q1 = sw[97];
    float k0 = sw[98], k1 = sw[99];
    float v0 = sw[100], v1 = sw[101];
    #pragma unroll
    for (int i = 0; i < 16; i++) {
        float xi = xv[i];
        q0 = fmaf(xi, sw[i*2+0],    q0);
        q1 = fmaf(xi, sw[i*2+1],    q1);
        k0 = fmaf(xi, sw[32+i*2+0], k0);
        k1 = fmaf(xi, sw[32+i*2+1], k1);
        v0 = fmaf(xi, sw[64+i*2+0], v0);
        v1 = fmaf(xi, sw[64+i*2+1], v1);
    }

    const float SC = 0.25f * 1.4426950408889634f;  // fold scale + log2e into Q
    g_q[idx] = make_float2(q0 * SC, q1 * SC);

    // Pack KV as duplicated half2 lanes: (k0,k0) (k1,k1) (v0,v0) (v1,v1)
    __half2 hk0 = __floats2half2_rn(k0, k0);
    __half2 hk1 = __floats2half2_rn(k1, k1);
    __half2 hv0 = __floats2half2_rn(v0, v0);
    __half2 hv1 = __floats2half2_rn(v1, v1);
    uint4 pk;
    pk.x = *reinterpret_cast<unsigned int*>(&hk0);
    pk.y = *reinterpret_cast<unsigned int*>(&hk1);
    pk.z = *reinterpret_cast<unsigned int*>(&hv0);
    pk.w = *reinterpret_cast<unsigned int*>(&hv1);
    g_kvh[idx] = pk;
}

// ---------------------------------------------------------------------------
// Kernel 2: attention, 4-way KV block split, 2 q-tokens per thread,
// f16x2 score+exp path: one MUFU (h2exp2) serves both tokens.
// Accumulate (l,a0,a1) as half2 in 16-iter chunks, flushed to f32.
// Grid (2, NSPLIT, BB), 256 threads.
// ---------------------------------------------------------------------------
__global__ void __launch_bounds__(256)
attn_kernel()
{
    __shared__ uint4 skv[256];   // packed half2 KV quarter (4 KB)

    int tid   = threadIdx.x;
    int b     = blockIdx.z;
    int split = blockIdx.y;
    int chunk = blockIdx.x;

    int idx0 = b * SS + chunk * 512 + tid;     // token A
    int idx1 = idx0 + 256;                     // token B

    uint4 kvrow = g_kvh[b * SS + split * 256 + tid];
    float2 qa = g_q[idx0];
    float2 qb = g_q[idx1];

    skv[tid] = kvrow;

    // Pack q pairs: (qa.x, qb.x), (qa.y, qb.y)
    __half2 qx = __floats2half2_rn(qa.x, qb.x);
    __half2 qy = __floats2half2_rn(qa.y, qb.y);
    __syncthreads();

    float l0 = 0.f, a00 = 0.f, a01 = 0.f;
    float l1 = 0.f, a10 = 0.f, a11 = 0.f;

    #pragma unroll
    for (int cch = 0; cch < 16; cch++) {
        __half2 lacc  = __floats2half2_rn(0.f, 0.f);
        __half2 a0acc = lacc, a1acc = lacc;
        #pragma unroll
        for (int t = 0; t < 16; t++) {
            uint4 kv = skv[cch * 16 + t];
            __half2 k00 = *reinterpret_cast<__half2*>(&kv.x);
            __half2 k11 = *reinterpret_cast<__half2*>(&kv.y);
            __half2 v00 = *reinterpret_cast<__half2*>(&kv.z);
            __half2 v11 = *reinterpret_cast<__half2*>(&kv.w);
            __half2 d = __hfma2(qy, k11, __hmul2(qx, k00));  // log2 scores
            __half2 p = h2exp2(d);                           // 2 exps, 1 MUFU
            lacc  = __hadd2(lacc, p);
            a0acc = __hfma2(p, v00, a0acc);
            a1acc = __hfma2(p, v11, a1acc);
        }
        float2 lf  = __half22float2(lacc);
        float2 a0f = __half22float2(a0acc);
        float2 a1f = __half22float2(a1acc);
        l0 += lf.x;  l1 += lf.y;
        a00 += a0f.x; a10 += a0f.y;
        a01 += a1f.x; a11 += a1f.y;
    }

    g_part[split * TOK + idx0] = make_float4(l0, a00, a01, 0.f);
    g_part[split * TOK + idx1] = make_float4(l1, a10, a11, 0.f);
}

// ---------------------------------------------------------------------------
// Kernel 3: epilogue, 1 thread/token, LN-folded weights (R11 measured-best).
// ---------------------------------------------------------------------------
__global__ void __launch_bounds__(256)
epilogue_kernel(const float* __restrict__ x,
                const float* __restrict__ Wu, const float* __restrict__ bu,
                float* __restrict__ out)
{
    __shared__ __align__(16) float sA[256], sO[256], sWu[32];
    __shared__ float sbu[16], scsA[16], sbA[16], scsO[16], sbO[16];

    int tid = threadIdx.x;
    int idx = blockIdx.x * 256 + tid;

    // Hoisted: 4 partial loads + 4 x loads (8 LDG.128 in flight)
    float4 p0 = g_part[0 * TOK + idx];
    float4 p1 = g_part[1 * TOK + idx];
    float4 p2 = g_part[2 * TOK + idx];
    float4 p3 = g_part[3 * TOK + idx];
    const float4* xp = reinterpret_cast<const float4*>(x + idx * DD);
    float4 xv0 = xp[0], xv1 = xp[1], xv2 = xp[2], xv3 = xp[3];

    sA[tid] = g_A[tid]; sO[tid] = g_O[tid];
    if (tid < 32) sWu[tid] = Wu[tid];
    if (tid < 16) {
        sbu[tid] = bu[tid];
        scsA[tid] = g_csA[tid]; sbA[tid] = g_bA[tid];
        scsO[tid] = g_csO[tid]; sbO[tid] = g_bO[tid];
    }
    __syncthreads();

    float l  = p0.x + p1.x + p2.x + p3.x;
    float a0 = p0.y + p1.y + p2.y + p3.y;
    float a1 = p0.z + p1.z + p2.z + p3.z;
    float inv = 1.0f / l;
    float c0 = a0 * inv, c1 = a1 * inv;

    float xr[16] = {xv0.x, xv0.y, xv0.z, xv0.w, xv1.x, xv1.y, xv1.z, xv1.w,
                    xv2.x, xv2.y, xv2.z, xv2.w, xv3.x, xv3.y, xv3.z, xv3.w};

    // u = ctx @ Wu + bu + x
    float u[16];
    #pragma unroll
    for (int i = 0; i < 16; i++)
        u[i] = fmaf(c0, sWu[i], fmaf(c1, sWu[16 + i], sbu[i])) + xr[i];

    // LN stats of u
    float su = 0.f, s2 = 0.f;
    #pragma unroll
    for (int i = 0; i < 16; i++) { su += u[i]; s2 = fmaf(u[i], u[i], s2); }
    float mu = su * (1.0f / 16.0f);
    float r  = rsqrtf(fmaf(-mu, mu, s2 * (1.0f / 16.0f)) + 1e-5f);

    // f = r*(u@A' - mu*csA) + bA
    float f[16];
    {
        float acc[16];
        #pragma unroll
        for (int j = 0; j < 16; j++) acc[j] = 0.f;
        #pragma unroll
        for (int i = 0; i < 16; i++) {
            float hv = u[i];
            const float4* wr = reinterpret_cast<const float4*>(sA + i * 16);
            #pragma unroll
            for (int j4 = 0; j4 < 4; j4++) {
                float4 w = wr[j4];
                acc[4*j4+0] = fmaf(hv, w.x, acc[4*j4+0]);
                acc[4*j4+1] = fmaf(hv, w.y, acc[4*j4+1]);
                acc[4*j4+2] = fmaf(hv, w.z, acc[4*j4+2]);
                acc[4*j4+3] = fmaf(hv, w.w, acc[4*j4+3]);
            }
        }
        #pragma unroll
        for (int j = 0; j < 16; j++)
            f[j] = fmaf(r, fmaf(-mu, scsA[j], acc[j]), sbA[j]);
    }

    // LN stats of f
    float sf = 0.f, sf2 = 0.f;
    #pragma unroll
    for (int i = 0; i < 16; i++) { sf += f[i]; sf2 = fmaf(f[i], f[i], sf2); }
    float mu2 = sf * (1.0f / 16.0f);
    float r2  = rsqrtf(fmaf(-mu2, mu2, sf2 * (1.0f / 16.0f)) + 1e-5f);

    // out = r2*(f@O' - mu2*csO) + bO
    float o[16];
    {
        float acc[16];
        #pragma unroll
        for (int j = 0; j < 16; j++) acc[j] = 0.f;
        #pragma unroll
        for (int i = 0; i < 16; i++) {
            float hv = f[i];
            const float4* wr = reinterpret_cast<const float4*>(sO + i * 16);
            #pragma unroll
            for (int j4 = 0; j4 < 4; j4++) {
                float4 w = wr[j4];
                acc[4*j4+0] = fmaf(hv, w.x, acc[4*j4+0]);
                acc[4*j4+1] = fmaf(hv, w.y, acc[4*j4+1]);
                acc[4*j4+2] = fmaf(hv, w.z, acc[4*j4+2]);
                acc[4*j4+3] = fmaf(hv, w.w, acc[4*j4+3]);
            }
        }
        #pragma unroll
        for (int j = 0; j < 16; j++)
            o[j] = fmaf(r2, fmaf(-mu2, scsO[j], acc[j]), sbO[j]);
    }

    float4* op = reinterpret_cast<float4*>(out + idx * DD);
    #pragma unroll
    for (int c4 = 0; c4 < 4; c4++)
        op[c4] = make_float4(o[4*c4+0], o[4*c4+1], o[4*c4+2], o[4*c4+3]);
}

// ---------------------------------------------------------------------------
extern "C" void kernel_launch(void* const* d_in, const int* in_sizes, int n_in,
                              void* d_out, int out_size)
{
    const float* x    = (const float*)d_in[0];
    const float* Wq   = (const float*)d_in[1];
    const float* bq   = (const float*)d_in[2];
    const float* Wk   = (const float*)d_in[3];
    const float* bk   = (const float*)d_in[4];
    const float* Wv   = (const float*)d_in[5];
    const float* bv   = (const float*)d_in[6];
    const float* Wu   = (const float*)d_in[7];
    const float* bu   = (const float*)d_in[8];
    const float* ln_g = (const float*)d_in[9];
    const float* ln_b = (const float*)d_in[10];
    const float* W1   = (const float*)d_in[11];
    const float* b1   = (const float*)d_in[12];
    const float* W2   = (const float*)d_in[13];
    const float* b2   = (const float*)d_in[14];
    const float* W3   = (const float*)d_in[15];
    const float* b3   = (const float*)d_in[16];
    const float* Wo   = (const float*)d_in[17];
    const float* bo   = (const float*)d_in[18];
    float* out = (float*)d_out;

    qkv_precomp_kernel<<<TOK / 256 + 1, 256>>>(x, Wq, bq, Wk, bk, Wv, bv,
                                               W1, b1, W2, b2, W3, b3,
                                               ln_g, ln_b, Wo, bo);

    dim3 agrid(2, NSPLIT, BB);
    attn_kernel<<<agrid, 256>>>();

    epilogue_kernel<<<TOK / 256, 256>>>(x, Wu, bu, out);
}